// round 3
// baseline (speedup 1.0000x reference)
#include <cuda_runtime.h>
#include <cuda_bf16.h>
#include <math.h>
#include <stdint.h>

// ---------------- problem constants ----------------
#define Nn 20000
#define Dd 128
#define Hh 256
#define Kk 16

// ---------------- grid constants -------------------
#define GG 48
#define NC (GG * GG * GG)        // 110592
#define XMIN (-6.0f)
#define CELL (0.25f)
#define INV_CELL (4.0f)

// ---------------- scratch (static device) ----------
__device__ int   g_cellOf[Nn];
__device__ int   g_cellCnt[NC];
__device__ int   g_cellStart[NC + 1];
__device__ int   g_cellCur[NC];
__device__ float4 g_pts[Nn];      // (x, y, z, sq) sorted by cell
__device__ int   g_ptIdx[Nn];     // original index, sorted by cell
__device__ int   g_knn[Nn * Kk];
__device__ int   g_deg[Nn];
__device__ float g_srcn[Nn];
__device__ __align__(16) float    g_bufH[Nn * Hh];   // fp32 hidden activations
__device__ __align__(16) uint32_t g_bufS[Nn * Hh];   // packed bf16 (hi|lo<<16) split of agg
__device__ __align__(16) uint32_t g_wt2[Hh * Hh];    // packed split of W^T  [n][k]

// ---------------- small helpers --------------------
__device__ __forceinline__ int cellc(float v) {
    int c = (int)floorf((v - XMIN) * INV_CELL);
    return min(max(c, 0), GG - 1);
}

__device__ __forceinline__ uint32_t pack_split(float v) {
    __nv_bfloat16 h = __float2bfloat16(v);
    float hf = __bfloat162float(h);
    __nv_bfloat16 l = __float2bfloat16(v - hf);
    unsigned short hs = *reinterpret_cast<unsigned short*>(&h);
    unsigned short ls = *reinterpret_cast<unsigned short*>(&l);
    return (uint32_t)hs | ((uint32_t)ls << 16);
}

__device__ __forceinline__ uint32_t smem_u32(const void* p) {
    uint32_t a;
    asm("{ .reg .u64 t; cvta.to.shared.u64 t, %1; cvt.u32.u64 %0, t; }"
        : "=r"(a) : "l"(p));
    return a;
}

__device__ __forceinline__ void ldsm4(uint32_t* r, uint32_t addr) {
    asm volatile("ldmatrix.sync.aligned.m8n8.x4.shared.b16 {%0,%1,%2,%3}, [%4];"
                 : "=r"(r[0]), "=r"(r[1]), "=r"(r[2]), "=r"(r[3]) : "r"(addr));
}

__device__ __forceinline__ void mma16816(float* c, const uint32_t* a,
                                         const uint32_t b0, const uint32_t b1) {
    asm volatile(
        "mma.sync.aligned.m16n8k16.row.col.f32.bf16.bf16.f32 "
        "{%0,%1,%2,%3}, {%4,%5,%6,%7}, {%8,%9}, {%0,%1,%2,%3};"
        : "+f"(c[0]), "+f"(c[1]), "+f"(c[2]), "+f"(c[3])
        : "r"(a[0]), "r"(a[1]), "r"(a[2]), "r"(a[3]), "r"(b0), "r"(b1));
}

// ---------------- setup kernels --------------------

__global__ void assign_kernel(const float* __restrict__ centers) {
    int i = blockIdx.x * blockDim.x + threadIdx.x;
    if (i >= Nn) return;
    float x = centers[3 * i], y = centers[3 * i + 1], z = centers[3 * i + 2];
    int cid = (cellc(z) * GG + cellc(y)) * GG + cellc(x);
    g_cellOf[i] = cid;
    atomicAdd(&g_cellCnt[cid], 1);
}

__global__ void scan_kernel() {
    const int per = NC / 1024;
    int t = threadIdx.x;
    int base = t * per;
    int s = 0;
    for (int i = 0; i < per; i++) s += g_cellCnt[base + i];

    int lane = t & 31, w = t >> 5;
    int v = s;
    for (int o = 1; o < 32; o <<= 1) {
        int n = __shfl_up_sync(0xffffffffu, v, o);
        if (lane >= o) v += n;
    }
    __shared__ int ws[32];
    if (lane == 31) ws[w] = v;
    __syncthreads();
    if (w == 0) {
        int xv = ws[lane];
        for (int o = 1; o < 32; o <<= 1) {
            int n = __shfl_up_sync(0xffffffffu, xv, o);
            if (lane >= o) xv += n;
        }
        ws[lane] = xv;
    }
    __syncthreads();
    int excl = v - s + (w ? ws[w - 1] : 0);
    int run = excl;
    for (int i = 0; i < per; i++) {
        int c = g_cellCnt[base + i];
        g_cellStart[base + i] = run;
        g_cellCur[base + i] = run;
        run += c;
    }
    if (t == 1023) g_cellStart[NC] = run;
}

__global__ void scatter_kernel(const float* __restrict__ centers) {
    int i = blockIdx.x * blockDim.x + threadIdx.x;
    if (i >= Nn) return;
    int cid = g_cellOf[i];
    int pos = atomicAdd(&g_cellCur[cid], 1);
    float x = centers[3 * i], y = centers[3 * i + 1], z = centers[3 * i + 2];
    float sq = fmaf(z, z, fmaf(y, y, x * x));
    g_pts[pos] = make_float4(x, y, z, sq);
    g_ptIdx[pos] = i;
}

// exact top-16 via ring expansion; one thread per SORTED point (warp locality)
__global__ void __launch_bounds__(128) knn_kernel() {
    int i = blockIdx.x * blockDim.x + threadIdx.x;
    if (i >= Nn) return;
    float4 q = g_pts[i];
    int orig = g_ptIdx[i];
    float qx = q.x, qy = q.y, qz = q.z, qsq = q.w;
    int cx = cellc(qx), cy = cellc(qy), cz = cellc(qz);

    float bd[Kk];
    int bi[Kk];
#pragma unroll
    for (int j = 0; j < Kk; j++) { bd[j] = 3.4e38f; bi[j] = 0; }

    int Rcov = max(max(max(cx, GG - 1 - cx), max(cy, GG - 1 - cy)),
                   max(cz, GG - 1 - cz));

    for (int R = 0; R <= Rcov; R++) {
        int zlo = max(cz - R, 0), zhi = min(cz + R, GG - 1);
        int ylo = max(cy - R, 0), yhi = min(cy + R, GG - 1);
        int xlo = max(cx - R, 0), xhi = min(cx + R, GG - 1);
        for (int z = zlo; z <= zhi; z++) {
            int adz = abs(z - cz);
            for (int y = ylo; y <= yhi; y++) {
                int dzy = max(adz, abs(y - cy));
                int runs[2][2];
                int nruns = 0;
                if (dzy == R) {
                    runs[0][0] = xlo; runs[0][1] = xhi; nruns = 1;
                } else {
                    if (cx - R >= 0) { runs[nruns][0] = cx - R; runs[nruns][1] = cx - R; nruns++; }
                    if (cx + R < GG) { runs[nruns][0] = cx + R; runs[nruns][1] = cx + R; nruns++; }
                }
                int rowbase = (z * GG + y) * GG;
                for (int r = 0; r < nruns; r++) {
                    int p0 = g_cellStart[rowbase + runs[r][0]];
                    int p1 = g_cellStart[rowbase + runs[r][1] + 1];
                    for (int p = p0; p < p1; p++) {
                        float4 c = g_pts[p];
                        float t1 = fmaf(qx, c.x, fmaf(qy, c.y, qz * c.z));
                        float d2 = fmaf(-2.0f, t1, qsq + c.w);
                        if (d2 < bd[Kk - 1]) {
                            int pid = g_ptIdx[p];
                            bd[Kk - 1] = d2; bi[Kk - 1] = pid;
#pragma unroll
                            for (int j = Kk - 1; j > 0; --j) {
                                if (bd[j] < bd[j - 1]) {
                                    float tf = bd[j]; bd[j] = bd[j - 1]; bd[j - 1] = tf;
                                    int ti = bi[j]; bi[j] = bi[j - 1]; bi[j - 1] = ti;
                                }
                            }
                        }
                    }
                }
            }
        }
        float bx = fminf(qx - (XMIN + (float)(cx - R) * CELL),
                         (XMIN + (float)(cx + R + 1) * CELL) - qx);
        float by = fminf(qy - (XMIN + (float)(cy - R) * CELL),
                         (XMIN + (float)(cy + R + 1) * CELL) - qy);
        float bz = fminf(qz - (XMIN + (float)(cz - R) * CELL),
                         (XMIN + (float)(cz + R + 1) * CELL) - qz);
        float b = fmaxf(fminf(bx, fminf(by, bz)), 0.0f);
        if (bd[Kk - 1] <= b * b) break;
    }

#pragma unroll
    for (int j = 0; j < Kk; j++) g_knn[orig * Kk + j] = bi[j];
}

__global__ void deg_kernel() {
    int e = blockIdx.x * blockDim.x + threadIdx.x;
    if (e < Nn * Kk) atomicAdd(&g_deg[g_knn[e]], 1);
}

__global__ void srcn_kernel() {
    int i = blockIdx.x * blockDim.x + threadIdx.x;
    if (i < Nn) g_srcn[i] = rsqrtf(fmaxf((float)g_deg[i], 1.0f));
}

// split-transpose of W[k][Hh] -> Wt2[n][Kd] packed (hi | lo<<16)
__global__ void convw_kernel(const float* __restrict__ W, int Kd) {
    int i = blockIdx.x * blockDim.x + threadIdx.x;
    if (i >= Kd * Hh) return;
    int k = i % Kd;
    int n = i / Kd;
    g_wt2[(size_t)n * Kd + k] = pack_split(W[(size_t)k * Hh + n]);
}

// agg[i,f] = 0.25 * sum_k h[knn[i,k], f] * srcn[knn[i,k]]  -> packed split
__global__ void aggregate_kernel(const float* __restrict__ Hin,
                                 uint32_t* __restrict__ Sout, int F) {
    __shared__ int jj[Kk];
    __shared__ float ss[Kk];
    int i = blockIdx.x;
    int t = threadIdx.x;
    if (t < Kk) {
        int j = g_knn[i * Kk + t];
        jj[t] = j;
        ss[t] = g_srcn[j];
    }
    __syncthreads();
    float acc = 0.0f;
#pragma unroll
    for (int k = 0; k < Kk; k++)
        acc = fmaf(Hin[(size_t)jj[k] * F + t], ss[k], acc);
    Sout[(size_t)i * F + t] = pack_split(acc * 0.25f);
}

// ---------------- tensor-core GEMM -----------------
#define BM 128
#define BN 128
#define BK 16
#define LDA 56   // padded row length (bf16 units) of a 48-wide expanded tile

__global__ void __launch_bounds__(256, 2) mma_gemm_kernel(
    const uint32_t* __restrict__ A2, const uint32_t* __restrict__ B2,
    const float* __restrict__ bias, float* __restrict__ C,
    int M, int Kd, int Nc) {
    __shared__ __align__(16) uint16_t As[BM * LDA];
    __shared__ __align__(16) uint16_t Bs[BN * LDA];

    int t = threadIdx.x;
    int lane = t & 31;
    int wid = t >> 5;
    int m0 = blockIdx.y * BM;
    int n0 = blockIdx.x * BN;

    int wm = wid & 3;
    int wn = wid >> 2;
    int m_base = wm * 32;
    int n_base = wn * 64;

    uint32_t as_base = smem_u32(As);
    uint32_t bs_base = smem_u32(Bs);

    uint32_t aaddr[2], baddr[4];
#pragma unroll
    for (int f = 0; f < 2; f++) {
        int row = m_base + f * 16 + (lane & 7) + (lane & 8);
        int koff = (lane & 16) ? 16 : 0;
        aaddr[f] = as_base + row * (LDA * 2) + koff;
    }
#pragma unroll
    for (int p = 0; p < 4; p++) {
        int row = n_base + p * 16 + (lane & 7) + ((lane & 16) >> 1);
        int koff = (lane & 8) ? 16 : 0;
        baddr[p] = bs_base + row * (LDA * 2) + koff;
    }

    float acc[2][8][4];
#pragma unroll
    for (int f = 0; f < 2; f++)
#pragma unroll
        for (int nf = 0; nf < 8; nf++)
#pragma unroll
            for (int c = 0; c < 4; c++) acc[f][nf][c] = 0.0f;

    uint32_t* As32 = (uint32_t*)As;
    uint32_t* Bs32 = (uint32_t*)Bs;

    const int steps = Kd / BK;
    for (int s = 0; s < steps; s++) {
        int k0 = s * BK;
#pragma unroll
        for (int v = 0; v < 2; v++) {
            int vec = t + v * 256;
            int row = vec >> 2, q = vec & 3;
            int gm = m0 + row;
            uint4 d = make_uint4(0u, 0u, 0u, 0u);
            if (gm < M)
                d = *(const uint4*)(A2 + (size_t)gm * Kd + k0 + q * 4);
            uint32_t h0 = d.x & 0xffffu, l0 = d.x >> 16;
            uint32_t h1 = d.y & 0xffffu, l1 = d.y >> 16;
            uint32_t h2 = d.z & 0xffffu, l2 = d.z >> 16;
            uint32_t h3 = d.w & 0xffffu, l3 = d.w >> 16;
            uint32_t hp0 = h0 | (h1 << 16), hp1 = h2 | (h3 << 16);
            uint32_t lp0 = l0 | (l1 << 16), lp1 = l2 | (l3 << 16);
            int b32 = row * (LDA / 2) + 2 * q;
            As32[b32 + 0] = hp0;  As32[b32 + 1] = hp1;
            As32[b32 + 8] = lp0;  As32[b32 + 9] = lp1;
            As32[b32 + 16] = hp0; As32[b32 + 17] = hp1;
        }
#pragma unroll
        for (int v = 0; v < 2; v++) {
            int vec = t + v * 256;
            int row = vec >> 2, q = vec & 3;
            uint4 d = *(const uint4*)(B2 + (size_t)(n0 + row) * Kd + k0 + q * 4);
            uint32_t h0 = d.x & 0xffffu, l0 = d.x >> 16;
            uint32_t h1 = d.y & 0xffffu, l1 = d.y >> 16;
            uint32_t h2 = d.z & 0xffffu, l2 = d.z >> 16;
            uint32_t h3 = d.w & 0xffffu, l3 = d.w >> 16;
            uint32_t hp0 = h0 | (h1 << 16), hp1 = h2 | (h3 << 16);
            uint32_t lp0 = l0 | (l1 << 16), lp1 = l2 | (l3 << 16);
            int b32 = row * (LDA / 2) + 2 * q;
            Bs32[b32 + 0] = hp0;  Bs32[b32 + 1] = hp1;
            Bs32[b32 + 8] = hp0;  Bs32[b32 + 9] = hp1;
            Bs32[b32 + 16] = lp0; Bs32[b32 + 17] = lp1;
        }
        __syncthreads();

#pragma unroll
        for (int kb = 0; kb < 3; kb++) {
            uint32_t a[2][4], b[4][4];
#pragma unroll
            for (int f = 0; f < 2; f++) ldsm4(a[f], aaddr[f] + kb * 32);
#pragma unroll
            for (int p = 0; p < 4; p++) ldsm4(b[p], baddr[p] + kb * 32);
#pragma unroll
            for (int f = 0; f < 2; f++)
#pragma unroll
                for (int p = 0; p < 4; p++) {
                    mma16816(acc[f][2 * p],     a[f], b[p][0], b[p][1]);
                    mma16816(acc[f][2 * p + 1], a[f], b[p][2], b[p][3]);
                }
        }
        __syncthreads();
    }

#pragma unroll
    for (int f = 0; f < 2; f++) {
#pragma unroll
        for (int nf = 0; nf < 8; nf++) {
            int col = n0 + n_base + nf * 8 + 2 * (lane & 3);
            float2 bv = *(const float2*)&bias[col];
            int row = m0 + m_base + f * 16 + (lane >> 2);
            if (row < M) {
                float2 o;
                o.x = fmaxf(acc[f][nf][0] + bv.x, 0.0f);
                o.y = fmaxf(acc[f][nf][1] + bv.y, 0.0f);
                *(float2*)(C + (size_t)row * Nc + col) = o;
            }
            int row2 = row + 8;
            if (row2 < M) {
                float2 o;
                o.x = fmaxf(acc[f][nf][2] + bv.x, 0.0f);
                o.y = fmaxf(acc[f][nf][3] + bv.y, 0.0f);
                *(float2*)(C + (size_t)row2 * Nc + col) = o;
            }
        }
    }
}

// out[i] = sigmoid(dot(h[i,:256], Wf) + bf) ; one warp per node
__global__ void final_kernel(const float* __restrict__ Hin,
                             const float* __restrict__ Wf,
                             const float* __restrict__ bf,
                             float* __restrict__ out) {
    int gwarp = (blockIdx.x * blockDim.x + threadIdx.x) >> 5;
    int lane = threadIdx.x & 31;
    if (gwarp >= Nn) return;
    float v = 0.0f;
#pragma unroll
    for (int tc = 0; tc < 8; tc++)
        v = fmaf(Hin[(size_t)gwarp * Hh + lane + tc * 32], Wf[lane + tc * 32], v);
#pragma unroll
    for (int off = 16; off > 0; off >>= 1)
        v += __shfl_xor_sync(0xffffffffu, v, off);
    if (lane == 0) {
        float z = v + bf[0];
        out[gwarp] = 1.0f / (1.0f + expf(-z));
    }
}

// ---------------- host launcher --------------------
extern "C" void kernel_launch(void* const* d_in, const int* in_sizes, int n_in,
                              void* d_out, int out_size) {
    const float* x       = (const float*)d_in[0];
    const float* centers = (const float*)d_in[1];
    const float* W0      = (const float*)d_in[2];
    const float* b0      = (const float*)d_in[3];
    const float* W1      = (const float*)d_in[4];
    const float* b1      = (const float*)d_in[5];
    const float* W2      = (const float*)d_in[6];
    const float* b2      = (const float*)d_in[7];
    const float* Wf      = (const float*)d_in[8];
    const float* bf      = (const float*)d_in[9];
    float* out = (float*)d_out;
    (void)in_sizes; (void)n_in; (void)out_size;

    void *pH, *pS, *pW, *pCnt, *pDeg;
    cudaGetSymbolAddress(&pH, g_bufH);
    cudaGetSymbolAddress(&pS, g_bufS);
    cudaGetSymbolAddress(&pW, g_wt2);
    cudaGetSymbolAddress(&pCnt, g_cellCnt);
    cudaGetSymbolAddress(&pDeg, g_deg);
    float*    Hbuf = (float*)pH;
    uint32_t* Sbuf = (uint32_t*)pS;
    uint32_t* Wbuf = (uint32_t*)pW;

    cudaMemsetAsync(pCnt, 0, NC * sizeof(int));
    cudaMemsetAsync(pDeg, 0, Nn * sizeof(int));
    assign_kernel<<<(Nn + 255) / 256, 256>>>(centers);
    scan_kernel<<<1, 1024>>>();
    scatter_kernel<<<(Nn + 255) / 256, 256>>>(centers);
    knn_kernel<<<(Nn + 127) / 128, 128>>>();
    deg_kernel<<<(Nn * Kk + 255) / 256, 256>>>();
    srcn_kernel<<<(Nn + 255) / 256, 256>>>();

    dim3 ggrid(Hh / BN, (Nn + BM - 1) / BM);

    // layer 0
    aggregate_kernel<<<Nn, Dd>>>(x, Sbuf, Dd);
    convw_kernel<<<(Dd * Hh + 255) / 256, 256>>>(W0, Dd);
    mma_gemm_kernel<<<ggrid, 256>>>(Sbuf, Wbuf, b0, Hbuf, Nn, Dd, Hh);

    // layer 1
    aggregate_kernel<<<Nn, Hh>>>(Hbuf, Sbuf, Hh);
    convw_kernel<<<(Hh * Hh + 255) / 256, 256>>>(W1, Hh);
    mma_gemm_kernel<<<ggrid, 256>>>(Sbuf, Wbuf, b1, Hbuf, Nn, Hh, Hh);

    // layer 2
    aggregate_kernel<<<Nn, Hh>>>(Hbuf, Sbuf, Hh);
    convw_kernel<<<(Hh * Hh + 255) / 256, 256>>>(W2, Hh);
    mma_gemm_kernel<<<ggrid, 256>>>(Sbuf, Wbuf, b2, Hbuf, Nn, Hh, Hh);

    // final
    final_kernel<<<(Nn * 32 + 255) / 256, 256>>>(Hbuf, Wf, bf, out);
}

// round 4
// speedup vs baseline: 1.1935x; 1.1935x over previous
#include <cuda_runtime.h>
#include <cuda_bf16.h>
#include <math.h>
#include <stdint.h>

// ---------------- problem constants ----------------
#define Nn 20000
#define Dd 128
#define Hh 256
#define Kk 16

// ---------------- grid constants -------------------
#define GG 48
#define NC (GG * GG * GG)        // 110592
#define XMIN (-6.0f)
#define CELL (0.25f)
#define INV_CELL (4.0f)
#define FINF 3.4e38f

// ---------------- scratch (static device) ----------
__device__ int   g_cellOf[Nn];
__device__ int   g_cellCnt[NC];
__device__ int   g_cellStart[NC + 1];
__device__ int   g_cellCur[NC];
__device__ float4 g_pts[Nn];      // (x, y, z, sq) sorted by cell
__device__ int   g_ptIdx[Nn];     // original index, sorted by cell
__device__ int   g_knn[Nn * Kk];
__device__ int   g_deg[Nn];
__device__ float g_srcn[Nn];
__device__ __align__(16) float    g_bufH[Nn * Hh];
__device__ __align__(16) uint32_t g_bufS[Nn * Hh];
__device__ __align__(16) uint32_t g_wt2[Hh * Hh];

// ---------------- small helpers --------------------
__device__ __forceinline__ int cellc(float v) {
    int c = (int)floorf((v - XMIN) * INV_CELL);
    return min(max(c, 0), GG - 1);
}

__device__ __forceinline__ uint32_t pack_split(float v) {
    __nv_bfloat16 h = __float2bfloat16(v);
    float hf = __bfloat162float(h);
    __nv_bfloat16 l = __float2bfloat16(v - hf);
    unsigned short hs = *reinterpret_cast<unsigned short*>(&h);
    unsigned short ls = *reinterpret_cast<unsigned short*>(&l);
    return (uint32_t)hs | ((uint32_t)ls << 16);
}

__device__ __forceinline__ uint32_t smem_u32(const void* p) {
    uint32_t a;
    asm("{ .reg .u64 t; cvta.to.shared.u64 t, %1; cvt.u32.u64 %0, t; }"
        : "=r"(a) : "l"(p));
    return a;
}

__device__ __forceinline__ void ldsm4(uint32_t* r, uint32_t addr) {
    asm volatile("ldmatrix.sync.aligned.m8n8.x4.shared.b16 {%0,%1,%2,%3}, [%4];"
                 : "=r"(r[0]), "=r"(r[1]), "=r"(r[2]), "=r"(r[3]) : "r"(addr));
}

__device__ __forceinline__ void mma16816(float* c, const uint32_t* a,
                                         const uint32_t b0, const uint32_t b1) {
    asm volatile(
        "mma.sync.aligned.m16n8k16.row.col.f32.bf16.bf16.f32 "
        "{%0,%1,%2,%3}, {%4,%5,%6,%7}, {%8,%9}, {%0,%1,%2,%3};"
        : "+f"(c[0]), "+f"(c[1]), "+f"(c[2]), "+f"(c[3])
        : "r"(a[0]), "r"(a[1]), "r"(a[2]), "r"(a[3]), "r"(b0), "r"(b1));
}

// warp arg-min: returns winning lane; v becomes warp-min (uniform)
__device__ __forceinline__ int warp_argmin(float& v, int lane) {
    int bl = lane;
#pragma unroll
    for (int off = 16; off > 0; off >>= 1) {
        float ov = __shfl_xor_sync(0xffffffffu, v, off);
        int   ol = __shfl_xor_sync(0xffffffffu, bl, off);
        if (ov < v || (ov == v && ol < bl)) { v = ov; bl = ol; }
    }
    return bl;
}

// ---------------- setup kernels --------------------

__global__ void assign_kernel(const float* __restrict__ centers) {
    int i = blockIdx.x * blockDim.x + threadIdx.x;
    if (i >= Nn) return;
    float x = centers[3 * i], y = centers[3 * i + 1], z = centers[3 * i + 2];
    int cid = (cellc(z) * GG + cellc(y)) * GG + cellc(x);
    g_cellOf[i] = cid;
    atomicAdd(&g_cellCnt[cid], 1);
}

__global__ void scan_kernel() {
    const int per = NC / 1024;
    int t = threadIdx.x;
    int base = t * per;
    int s = 0;
    for (int i = 0; i < per; i++) s += g_cellCnt[base + i];

    int lane = t & 31, w = t >> 5;
    int v = s;
    for (int o = 1; o < 32; o <<= 1) {
        int n = __shfl_up_sync(0xffffffffu, v, o);
        if (lane >= o) v += n;
    }
    __shared__ int ws[32];
    if (lane == 31) ws[w] = v;
    __syncthreads();
    if (w == 0) {
        int xv = ws[lane];
        for (int o = 1; o < 32; o <<= 1) {
            int n = __shfl_up_sync(0xffffffffu, xv, o);
            if (lane >= o) xv += n;
        }
        ws[lane] = xv;
    }
    __syncthreads();
    int excl = v - s + (w ? ws[w - 1] : 0);
    int run = excl;
    for (int i = 0; i < per; i++) {
        int c = g_cellCnt[base + i];
        g_cellStart[base + i] = run;
        g_cellCur[base + i] = run;
        run += c;
    }
    if (t == 1023) g_cellStart[NC] = run;
}

__global__ void scatter_kernel(const float* __restrict__ centers) {
    int i = blockIdx.x * blockDim.x + threadIdx.x;
    if (i >= Nn) return;
    int cid = g_cellOf[i];
    int pos = atomicAdd(&g_cellCur[cid], 1);
    float x = centers[3 * i], y = centers[3 * i + 1], z = centers[3 * i + 2];
    float sq = fmaf(z, z, fmaf(y, y, x * x));
    g_pts[pos] = make_float4(x, y, z, sq);
    g_ptIdx[pos] = i;
}

// ---------------- warp-per-query exact kNN ----------------
__global__ void __launch_bounds__(256) knn_kernel() {
    int gw = (blockIdx.x * blockDim.x + threadIdx.x) >> 5;
    int lane = threadIdx.x & 31;
    if (gw >= Nn) return;
    float4 q = g_pts[gw];
    int orig = g_ptIdx[gw];
    float qx = q.x, qy = q.y, qz = q.z, qsq = q.w;
    int cx = cellc(qx), cy = cellc(qy), cz = cellc(qz);

    float bd[Kk];
    int bi[Kk];
#pragma unroll
    for (int j = 0; j < Kk; j++) { bd[j] = FINF; bi[j] = 0; }
    int cnt = 0;          // accepted inserts (local)
    float gth = FINF;     // warp-uniform upper bound on global 16th

    int Rcov = max(max(max(cx, GG - 1 - cx), max(cy, GG - 1 - cy)),
                   max(cz, GG - 1 - cz));

    for (int R = 0; R <= Rcov; R++) {
        int zlo = max(cz - R, 0), zhi = min(cz + R, GG - 1);
        int ylo = max(cy - R, 0), yhi = min(cy + R, GG - 1);
        int xlo = max(cx - R, 0), xhi = min(cx + R, GG - 1);
        for (int z = zlo; z <= zhi; z++) {
            int adz = abs(z - cz);
            for (int y = ylo; y <= yhi; y++) {
                int dzy = max(adz, abs(y - cy));
                int runs[2][2];
                int nruns = 0;
                if (dzy == R) {
                    runs[0][0] = xlo; runs[0][1] = xhi; nruns = 1;
                } else {
                    if (cx - R >= 0) { runs[nruns][0] = cx - R; runs[nruns][1] = cx - R; nruns++; }
                    if (cx + R < GG) { runs[nruns][0] = cx + R; runs[nruns][1] = cx + R; nruns++; }
                }
                int rowbase = (z * GG + y) * GG;
                for (int r = 0; r < nruns; r++) {
                    int p0 = g_cellStart[rowbase + runs[r][0]];
                    int p1 = g_cellStart[rowbase + runs[r][1] + 1];
                    for (int p = p0 + lane; p < p1; p += 32) {
                        float4 c = g_pts[p];
                        float t1 = fmaf(qx, c.x, fmaf(qy, c.y, qz * c.z));
                        float d2 = fmaf(-2.0f, t1, qsq + c.w);
                        if (d2 < bd[Kk - 1] && d2 < gth) {
                            int pid = g_ptIdx[p];
                            bd[Kk - 1] = d2; bi[Kk - 1] = pid;
                            cnt++;
#pragma unroll
                            for (int j = Kk - 1; j > 0; --j) {
                                if (bd[j] < bd[j - 1]) {
                                    float tf = bd[j]; bd[j] = bd[j - 1]; bd[j - 1] = tf;
                                    int ti = bi[j]; bi[j] = bi[j - 1]; bi[j - 1] = ti;
                                }
                            }
                        }
                    }
                }
            }
        }
        // ---- stopping rule: exact global 16th via merge on a copy ----
        int tot = __reduce_add_sync(0xffffffffu, min(cnt, Kk));
        if (tot >= Kk) {
            float tmp[Kk];
#pragma unroll
            for (int j = 0; j < Kk; j++) tmp[j] = bd[j];
            float last = FINF;
#pragma unroll
            for (int r16 = 0; r16 < Kk; r16++) {
                float v = tmp[0];
                int bl = warp_argmin(v, lane);
                last = v;
                if (lane == bl) {
#pragma unroll
                    for (int j = 0; j < Kk - 1; j++) tmp[j] = tmp[j + 1];
                    tmp[Kk - 1] = FINF;
                }
            }
            gth = last;   // uniform
            float bx = fminf(qx - (XMIN + (float)(cx - R) * CELL),
                             (XMIN + (float)(cx + R + 1) * CELL) - qx);
            float by = fminf(qy - (XMIN + (float)(cy - R) * CELL),
                             (XMIN + (float)(cy + R + 1) * CELL) - qy);
            float bz = fminf(qz - (XMIN + (float)(cz - R) * CELL),
                             (XMIN + (float)(cz + R + 1) * CELL) - qz);
            float b = fmaxf(fminf(bx, fminf(by, bz)), 0.0f);
            if (gth <= b * b) break;
        }
    }

    // ---- final merge with indices: winner lane stores result r ----
#pragma unroll
    for (int r16 = 0; r16 < Kk; r16++) {
        float v = bd[0];
        int bl = warp_argmin(v, lane);
        if (lane == bl) {
            g_knn[orig * Kk + r16] = bi[0];
#pragma unroll
            for (int j = 0; j < Kk - 1; j++) { bd[j] = bd[j + 1]; bi[j] = bi[j + 1]; }
            bd[Kk - 1] = FINF;
        }
    }
}

__global__ void deg_kernel() {
    int e = blockIdx.x * blockDim.x + threadIdx.x;
    if (e < Nn * Kk) atomicAdd(&g_deg[g_knn[e]], 1);
}

__global__ void srcn_kernel() {
    int i = blockIdx.x * blockDim.x + threadIdx.x;
    if (i < Nn) g_srcn[i] = rsqrtf(fmaxf((float)g_deg[i], 1.0f));
}

// split-transpose of W[k][Hh] -> Wt2[n][Kd] packed (hi | lo<<16)
__global__ void convw_kernel(const float* __restrict__ W, int Kd) {
    int i = blockIdx.x * blockDim.x + threadIdx.x;
    if (i >= Kd * Hh) return;
    int k = i % Kd;
    int n = i / Kd;
    g_wt2[(size_t)n * Kd + k] = pack_split(W[(size_t)k * Hh + n]);
}

// agg[i,f] = 0.25 * sum_k h[knn[i,k], f] * srcn[knn[i,k]]  -> packed split
__global__ void aggregate_kernel(const float* __restrict__ Hin,
                                 uint32_t* __restrict__ Sout, int F) {
    __shared__ int jj[Kk];
    __shared__ float ss[Kk];
    int i = blockIdx.x;
    int t = threadIdx.x;
    if (t < Kk) {
        int j = g_knn[i * Kk + t];
        jj[t] = j;
        ss[t] = g_srcn[j];
    }
    __syncthreads();
    float acc = 0.0f;
#pragma unroll
    for (int k = 0; k < Kk; k++)
        acc = fmaf(Hin[(size_t)jj[k] * F + t], ss[k], acc);
    Sout[(size_t)i * F + t] = pack_split(acc * 0.25f);
}

// ---------------- tensor-core GEMM -----------------
#define BM 128
#define BN 128
#define BK 16
#define LDA 56

__global__ void __launch_bounds__(256, 2) mma_gemm_kernel(
    const uint32_t* __restrict__ A2, const uint32_t* __restrict__ B2,
    const float* __restrict__ bias, float* __restrict__ C,
    int M, int Kd, int Nc) {
    __shared__ __align__(16) uint16_t As[BM * LDA];
    __shared__ __align__(16) uint16_t Bs[BN * LDA];

    int t = threadIdx.x;
    int lane = t & 31;
    int wid = t >> 5;
    int m0 = blockIdx.y * BM;
    int n0 = blockIdx.x * BN;

    int wm = wid & 3;
    int wn = wid >> 2;
    int m_base = wm * 32;
    int n_base = wn * 64;

    uint32_t as_base = smem_u32(As);
    uint32_t bs_base = smem_u32(Bs);

    uint32_t aaddr[2], baddr[4];
#pragma unroll
    for (int f = 0; f < 2; f++) {
        int row = m_base + f * 16 + (lane & 7) + (lane & 8);
        int koff = (lane & 16) ? 16 : 0;
        aaddr[f] = as_base + row * (LDA * 2) + koff;
    }
#pragma unroll
    for (int p = 0; p < 4; p++) {
        int row = n_base + p * 16 + (lane & 7) + ((lane & 16) >> 1);
        int koff = (lane & 8) ? 16 : 0;
        baddr[p] = bs_base + row * (LDA * 2) + koff;
    }

    float acc[2][8][4];
#pragma unroll
    for (int f = 0; f < 2; f++)
#pragma unroll
        for (int nf = 0; nf < 8; nf++)
#pragma unroll
            for (int c = 0; c < 4; c++) acc[f][nf][c] = 0.0f;

    uint32_t* As32 = (uint32_t*)As;
    uint32_t* Bs32 = (uint32_t*)Bs;

    const int steps = Kd / BK;
    for (int s = 0; s < steps; s++) {
        int k0 = s * BK;
#pragma unroll
        for (int v = 0; v < 2; v++) {
            int vec = t + v * 256;
            int row = vec >> 2, q = vec & 3;
            int gm = m0 + row;
            uint4 d = make_uint4(0u, 0u, 0u, 0u);
            if (gm < M)
                d = *(const uint4*)(A2 + (size_t)gm * Kd + k0 + q * 4);
            uint32_t h0 = d.x & 0xffffu, l0 = d.x >> 16;
            uint32_t h1 = d.y & 0xffffu, l1 = d.y >> 16;
            uint32_t h2 = d.z & 0xffffu, l2 = d.z >> 16;
            uint32_t h3 = d.w & 0xffffu, l3 = d.w >> 16;
            uint32_t hp0 = h0 | (h1 << 16), hp1 = h2 | (h3 << 16);
            uint32_t lp0 = l0 | (l1 << 16), lp1 = l2 | (l3 << 16);
            int b32 = row * (LDA / 2) + 2 * q;
            As32[b32 + 0] = hp0;  As32[b32 + 1] = hp1;
            As32[b32 + 8] = lp0;  As32[b32 + 9] = lp1;
            As32[b32 + 16] = hp0; As32[b32 + 17] = hp1;
        }
#pragma unroll
        for (int v = 0; v < 2; v++) {
            int vec = t + v * 256;
            int row = vec >> 2, q = vec & 3;
            uint4 d = *(const uint4*)(B2 + (size_t)(n0 + row) * Kd + k0 + q * 4);
            uint32_t h0 = d.x & 0xffffu, l0 = d.x >> 16;
            uint32_t h1 = d.y & 0xffffu, l1 = d.y >> 16;
            uint32_t h2 = d.z & 0xffffu, l2 = d.z >> 16;
            uint32_t h3 = d.w & 0xffffu, l3 = d.w >> 16;
            uint32_t hp0 = h0 | (h1 << 16), hp1 = h2 | (h3 << 16);
            uint32_t lp0 = l0 | (l1 << 16), lp1 = l2 | (l3 << 16);
            int b32 = row * (LDA / 2) + 2 * q;
            Bs32[b32 + 0] = hp0;  Bs32[b32 + 1] = hp1;
            Bs32[b32 + 8] = hp0;  Bs32[b32 + 9] = hp1;
            Bs32[b32 + 16] = lp0; Bs32[b32 + 17] = lp1;
        }
        __syncthreads();

#pragma unroll
        for (int kb = 0; kb < 3; kb++) {
            uint32_t a[2][4], b[4][4];
#pragma unroll
            for (int f = 0; f < 2; f++) ldsm4(a[f], aaddr[f] + kb * 32);
#pragma unroll
            for (int p = 0; p < 4; p++) ldsm4(b[p], baddr[p] + kb * 32);
#pragma unroll
            for (int f = 0; f < 2; f++)
#pragma unroll
                for (int p = 0; p < 4; p++) {
                    mma16816(acc[f][2 * p],     a[f], b[p][0], b[p][1]);
                    mma16816(acc[f][2 * p + 1], a[f], b[p][2], b[p][3]);
                }
        }
        __syncthreads();
    }

#pragma unroll
    for (int f = 0; f < 2; f++) {
#pragma unroll
        for (int nf = 0; nf < 8; nf++) {
            int col = n0 + n_base + nf * 8 + 2 * (lane & 3);
            float2 bv = *(const float2*)&bias[col];
            int row = m0 + m_base + f * 16 + (lane >> 2);
            if (row < M) {
                float2 o;
                o.x = fmaxf(acc[f][nf][0] + bv.x, 0.0f);
                o.y = fmaxf(acc[f][nf][1] + bv.y, 0.0f);
                *(float2*)(C + (size_t)row * Nc + col) = o;
            }
            int row2 = row + 8;
            if (row2 < M) {
                float2 o;
                o.x = fmaxf(acc[f][nf][2] + bv.x, 0.0f);
                o.y = fmaxf(acc[f][nf][3] + bv.y, 0.0f);
                *(float2*)(C + (size_t)row2 * Nc + col) = o;
            }
        }
    }
}

// out[i] = sigmoid(dot(h[i,:256], Wf) + bf) ; one warp per node
__global__ void final_kernel(const float* __restrict__ Hin,
                             const float* __restrict__ Wf,
                             const float* __restrict__ bf,
                             float* __restrict__ out) {
    int gwarp = (blockIdx.x * blockDim.x + threadIdx.x) >> 5;
    int lane = threadIdx.x & 31;
    if (gwarp >= Nn) return;
    float v = 0.0f;
#pragma unroll
    for (int tc = 0; tc < 8; tc++)
        v = fmaf(Hin[(size_t)gwarp * Hh + lane + tc * 32], Wf[lane + tc * 32], v);
#pragma unroll
    for (int off = 16; off > 0; off >>= 1)
        v += __shfl_xor_sync(0xffffffffu, v, off);
    if (lane == 0) {
        float z = v + bf[0];
        out[gwarp] = 1.0f / (1.0f + expf(-z));
    }
}

// ---------------- host launcher --------------------
extern "C" void kernel_launch(void* const* d_in, const int* in_sizes, int n_in,
                              void* d_out, int out_size) {
    const float* x       = (const float*)d_in[0];
    const float* centers = (const float*)d_in[1];
    const float* W0      = (const float*)d_in[2];
    const float* b0      = (const float*)d_in[3];
    const float* W1      = (const float*)d_in[4];
    const float* b1      = (const float*)d_in[5];
    const float* W2      = (const float*)d_in[6];
    const float* b2      = (const float*)d_in[7];
    const float* Wf      = (const float*)d_in[8];
    const float* bf      = (const float*)d_in[9];
    float* out = (float*)d_out;
    (void)in_sizes; (void)n_in; (void)out_size;

    void *pH, *pS, *pW, *pCnt, *pDeg;
    cudaGetSymbolAddress(&pH, g_bufH);
    cudaGetSymbolAddress(&pS, g_bufS);
    cudaGetSymbolAddress(&pW, g_wt2);
    cudaGetSymbolAddress(&pCnt, g_cellCnt);
    cudaGetSymbolAddress(&pDeg, g_deg);
    float*    Hbuf = (float*)pH;
    uint32_t* Sbuf = (uint32_t*)pS;
    uint32_t* Wbuf = (uint32_t*)pW;

    cudaMemsetAsync(pCnt, 0, NC * sizeof(int));
    cudaMemsetAsync(pDeg, 0, Nn * sizeof(int));
    assign_kernel<<<(Nn + 255) / 256, 256>>>(centers);
    scan_kernel<<<1, 1024>>>();
    scatter_kernel<<<(Nn + 255) / 256, 256>>>(centers);
    knn_kernel<<<(Nn * 32 + 255) / 256, 256>>>();
    deg_kernel<<<(Nn * Kk + 255) / 256, 256>>>();
    srcn_kernel<<<(Nn + 255) / 256, 256>>>();

    dim3 ggrid(Hh / BN, (Nn + BM - 1) / BM);

    // layer 0
    aggregate_kernel<<<Nn, Dd>>>(x, Sbuf, Dd);
    convw_kernel<<<(Dd * Hh + 255) / 256, 256>>>(W0, Dd);
    mma_gemm_kernel<<<ggrid, 256>>>(Sbuf, Wbuf, b0, Hbuf, Nn, Dd, Hh);

    // layer 1
    aggregate_kernel<<<Nn, Hh>>>(Hbuf, Sbuf, Hh);
    convw_kernel<<<(Hh * Hh + 255) / 256, 256>>>(W1, Hh);
    mma_gemm_kernel<<<ggrid, 256>>>(Sbuf, Wbuf, b1, Hbuf, Nn, Hh, Hh);

    // layer 2
    aggregate_kernel<<<Nn, Hh>>>(Hbuf, Sbuf, Hh);
    convw_kernel<<<(Hh * Hh + 255) / 256, 256>>>(W2, Hh);
    mma_gemm_kernel<<<ggrid, 256>>>(Sbuf, Wbuf, b2, Hbuf, Nn, Hh, Hh);

    // final
    final_kernel<<<(Nn * 32 + 255) / 256, 256>>>(Hbuf, Wf, bf, out);
}

// round 5
// speedup vs baseline: 2.6664x; 2.2342x over previous
#include <cuda_runtime.h>
#include <cuda_bf16.h>
#include <math.h>
#include <stdint.h>

// ---------------- problem constants ----------------
#define Nn 20000
#define Dd 128
#define Hh 256
#define Kk 16

// ---------------- grid constants -------------------
#define GG 24
#define NC (GG * GG * GG)        // 13824
#define XMIN (-6.0f)
#define CELL (0.5f)
#define INV_CELL (2.0f)
#define FINF 3.4e38f
#define FULLM 0xffffffffu

// ---------------- scratch (static device) ----------
__device__ int   g_cellOf[Nn];
__device__ int   g_cellCnt[NC];
__device__ int   g_cellStart[NC + 1];
__device__ int   g_cellCur[NC];
__device__ float4 g_pts[Nn];      // (x, y, z, sq) sorted by cell
__device__ int   g_ptIdx[Nn];     // original index, sorted by cell
__device__ int   g_knn[Nn * Kk];
__device__ int   g_deg[Nn];
__device__ float g_srcn[Nn];
__device__ __align__(16) float    g_bufH[Nn * Hh];
__device__ __align__(16) uint32_t g_bufS[Nn * Hh];
__device__ __align__(16) uint32_t g_wt2[Hh * Hh];

// ---------------- small helpers --------------------
__device__ __forceinline__ int cellc(float v) {
    int c = (int)floorf((v - XMIN) * INV_CELL);
    return min(max(c, 0), GG - 1);
}

__device__ __forceinline__ uint32_t pack_split(float v) {
    __nv_bfloat16 h = __float2bfloat16(v);
    float hf = __bfloat162float(h);
    __nv_bfloat16 l = __float2bfloat16(v - hf);
    unsigned short hs = *reinterpret_cast<unsigned short*>(&h);
    unsigned short ls = *reinterpret_cast<unsigned short*>(&l);
    return (uint32_t)hs | ((uint32_t)ls << 16);
}

__device__ __forceinline__ uint32_t smem_u32(const void* p) {
    uint32_t a;
    asm("{ .reg .u64 t; cvta.to.shared.u64 t, %1; cvt.u32.u64 %0, t; }"
        : "=r"(a) : "l"(p));
    return a;
}

__device__ __forceinline__ void ldsm4(uint32_t* r, uint32_t addr) {
    asm volatile("ldmatrix.sync.aligned.m8n8.x4.shared.b16 {%0,%1,%2,%3}, [%4];"
                 : "=r"(r[0]), "=r"(r[1]), "=r"(r[2]), "=r"(r[3]) : "r"(addr));
}

__device__ __forceinline__ void mma16816(float* c, const uint32_t* a,
                                         const uint32_t b0, const uint32_t b1) {
    asm volatile(
        "mma.sync.aligned.m16n8k16.row.col.f32.bf16.bf16.f32 "
        "{%0,%1,%2,%3}, {%4,%5,%6,%7}, {%8,%9}, {%0,%1,%2,%3};"
        : "+f"(c[0]), "+f"(c[1]), "+f"(c[2]), "+f"(c[3])
        : "r"(a[0]), "r"(a[1]), "r"(a[2]), "r"(a[3]), "r"(b0), "r"(b1));
}

// ---------------- setup kernels --------------------

__global__ void assign_kernel(const float* __restrict__ centers) {
    int i = blockIdx.x * blockDim.x + threadIdx.x;
    if (i >= Nn) return;
    float x = centers[3 * i], y = centers[3 * i + 1], z = centers[3 * i + 2];
    int cid = (cellc(z) * GG + cellc(y)) * GG + cellc(x);
    g_cellOf[i] = cid;
    atomicAdd(&g_cellCnt[cid], 1);
}

// single-block exclusive scan over NC cells (1024 threads, 14 cells each, guarded)
__global__ void scan_kernel() {
    const int per = 14;   // 1024*14 = 14336 >= NC
    int t = threadIdx.x;
    int base = t * per;
    int s = 0;
    for (int i = 0; i < per; i++) {
        int idx = base + i;
        s += (idx < NC) ? g_cellCnt[idx] : 0;
    }

    int lane = t & 31, w = t >> 5;
    int v = s;
    for (int o = 1; o < 32; o <<= 1) {
        int n = __shfl_up_sync(FULLM, v, o);
        if (lane >= o) v += n;
    }
    __shared__ int ws[32];
    if (lane == 31) ws[w] = v;
    __syncthreads();
    if (w == 0) {
        int xv = ws[lane];
        for (int o = 1; o < 32; o <<= 1) {
            int n = __shfl_up_sync(FULLM, xv, o);
            if (lane >= o) xv += n;
        }
        ws[lane] = xv;
    }
    __syncthreads();
    int excl = v - s + (w ? ws[w - 1] : 0);
    int run = excl;
    for (int i = 0; i < per; i++) {
        int idx = base + i;
        if (idx < NC) {
            int c = g_cellCnt[idx];
            g_cellStart[idx] = run;
            g_cellCur[idx] = run;
            run += c;
        }
    }
    if (t == 1023) g_cellStart[NC] = Nn;
}

__global__ void scatter_kernel(const float* __restrict__ centers) {
    int i = blockIdx.x * blockDim.x + threadIdx.x;
    if (i >= Nn) return;
    int cid = g_cellOf[i];
    int pos = atomicAdd(&g_cellCur[cid], 1);
    float x = centers[3 * i], y = centers[3 * i + 1], z = centers[3 * i + 2];
    float sq = fmaf(z, z, fmaf(y, y, x * x));
    g_pts[pos] = make_float4(x, y, z, sq);
    g_ptIdx[pos] = i;
}

// ---------------- warp-per-query exact kNN ----------------
// Warp-distributed sorted top-16: lane j holds j-th best (d2, idx), ascending.
__global__ void __launch_bounds__(256) knn_kernel() {
    int gw = (blockIdx.x * blockDim.x + threadIdx.x) >> 5;
    int lane = threadIdx.x & 31;
    if (gw >= Nn) return;
    float4 q = g_pts[gw];
    int orig = g_ptIdx[gw];
    float qx = q.x, qy = q.y, qz = q.z, qsq = q.w;
    int cx = cellc(qx), cy = cellc(qy), cz = cellc(qz);

    float ld = FINF;   // distributed list: lane j = j-th smallest d2
    int   li = 0;
    float gth = FINF;  // current 16th-best (uniform)

    int Rcov = max(max(max(cx, GG - 1 - cx), max(cy, GG - 1 - cy)),
                   max(cz, GG - 1 - cz));

    for (int R = 0; R <= Rcov; R++) {
        int zlo = max(cz - R, 0), zhi = min(cz + R, GG - 1);
        int ylo = max(cy - R, 0), yhi = min(cy + R, GG - 1);
        int xlo = max(cx - R, 0), xhi = min(cx + R, GG - 1);
        for (int z = zlo; z <= zhi; z++) {
            int adz = abs(z - cz);
            for (int y = ylo; y <= yhi; y++) {
                int dzy = max(adz, abs(y - cy));
                int runs[2][2];
                int nruns = 0;
                if (dzy == R) {
                    runs[0][0] = xlo; runs[0][1] = xhi; nruns = 1;
                } else {
                    if (cx - R >= 0) { runs[nruns][0] = cx - R; runs[nruns][1] = cx - R; nruns++; }
                    if (cx + R < GG) { runs[nruns][0] = cx + R; runs[nruns][1] = cx + R; nruns++; }
                }
                int rowbase = (z * GG + y) * GG;
                for (int r = 0; r < nruns; r++) {
                    int p0 = g_cellStart[rowbase + runs[r][0]];
                    int p1 = g_cellStart[rowbase + runs[r][1] + 1];
                    for (int pb = p0; pb < p1; pb += 32) {
                        int p = pb + lane;
                        float d2 = FINF;
                        int pid = 0;
                        if (p < p1) {
                            float4 c = g_pts[p];
                            float t1 = fmaf(qx, c.x, fmaf(qy, c.y, qz * c.z));
                            d2 = fmaf(-2.0f, t1, qsq + c.w);
                            pid = g_ptIdx[p];
                        }
                        unsigned mask = __ballot_sync(FULLM, d2 < gth);
                        while (mask) {
                            int src = __ffs(mask) - 1;
                            mask &= mask - 1;
                            float nd = __shfl_sync(FULLM, d2, src);
                            int   ni = __shfl_sync(FULLM, pid, src);
                            if (nd >= gth) continue;           // uniform
                            unsigned le = __ballot_sync(FULLM, ld <= nd);
                            int pos = __popc(le);
                            float pd = __shfl_up_sync(FULLM, ld, 1);
                            int   pi = __shfl_up_sync(FULLM, li, 1);
                            if (lane >= pos) { ld = pd; li = pi; }
                            if (lane == pos) { ld = nd; li = ni; }
                            gth = __shfl_sync(FULLM, ld, 15);
                        }
                    }
                }
            }
        }
        // stopping rule: gth is exact 16th best so far (uniform)
        if (gth < FINF) {
            float bx = fminf(qx - (XMIN + (float)(cx - R) * CELL),
                             (XMIN + (float)(cx + R + 1) * CELL) - qx);
            float by = fminf(qy - (XMIN + (float)(cy - R) * CELL),
                             (XMIN + (float)(cy + R + 1) * CELL) - qy);
            float bz = fminf(qz - (XMIN + (float)(cz - R) * CELL),
                             (XMIN + (float)(cz + R + 1) * CELL) - qz);
            float b = fmaxf(fminf(bx, fminf(by, bz)), 0.0f);
            if (gth <= b * b) break;
        }
    }

    if (lane < Kk) g_knn[orig * Kk + lane] = li;
}

__global__ void deg_kernel() {
    int e = blockIdx.x * blockDim.x + threadIdx.x;
    if (e < Nn * Kk) atomicAdd(&g_deg[g_knn[e]], 1);
}

__global__ void srcn_kernel() {
    int i = blockIdx.x * blockDim.x + threadIdx.x;
    if (i < Nn) g_srcn[i] = rsqrtf(fmaxf((float)g_deg[i], 1.0f));
}

// split-transpose of W[k][Hh] -> Wt2[n][Kd] packed (hi | lo<<16)
__global__ void convw_kernel(const float* __restrict__ W, int Kd) {
    int i = blockIdx.x * blockDim.x + threadIdx.x;
    if (i >= Kd * Hh) return;
    int k = i % Kd;
    int n = i / Kd;
    g_wt2[(size_t)n * Kd + k] = pack_split(W[(size_t)k * Hh + n]);
}

// agg[i,f] = 0.25 * sum_k h[knn[i,k], f] * srcn[knn[i,k]]  -> packed split
__global__ void aggregate_kernel(const float* __restrict__ Hin,
                                 uint32_t* __restrict__ Sout, int F) {
    __shared__ int jj[Kk];
    __shared__ float ss[Kk];
    int i = blockIdx.x;
    int t = threadIdx.x;
    if (t < Kk) {
        int j = g_knn[i * Kk + t];
        jj[t] = j;
        ss[t] = g_srcn[j];
    }
    __syncthreads();
    float acc = 0.0f;
#pragma unroll
    for (int k = 0; k < Kk; k++)
        acc = fmaf(Hin[(size_t)jj[k] * F + t], ss[k], acc);
    Sout[(size_t)i * F + t] = pack_split(acc * 0.25f);
}

// ---------------- tensor-core GEMM -----------------
#define BM 128
#define BN 128
#define BK 16
#define LDA 56

__global__ void __launch_bounds__(256, 2) mma_gemm_kernel(
    const uint32_t* __restrict__ A2, const uint32_t* __restrict__ B2,
    const float* __restrict__ bias, float* __restrict__ C,
    int M, int Kd, int Nc) {
    __shared__ __align__(16) uint16_t As[BM * LDA];
    __shared__ __align__(16) uint16_t Bs[BN * LDA];

    int t = threadIdx.x;
    int lane = t & 31;
    int wid = t >> 5;
    int m0 = blockIdx.y * BM;
    int n0 = blockIdx.x * BN;

    int wm = wid & 3;
    int wn = wid >> 2;
    int m_base = wm * 32;
    int n_base = wn * 64;

    uint32_t as_base = smem_u32(As);
    uint32_t bs_base = smem_u32(Bs);

    uint32_t aaddr[2], baddr[4];
#pragma unroll
    for (int f = 0; f < 2; f++) {
        int row = m_base + f * 16 + (lane & 7) + (lane & 8);
        int koff = (lane & 16) ? 16 : 0;
        aaddr[f] = as_base + row * (LDA * 2) + koff;
    }
#pragma unroll
    for (int p = 0; p < 4; p++) {
        int row = n_base + p * 16 + (lane & 7) + ((lane & 16) >> 1);
        int koff = (lane & 8) ? 16 : 0;
        baddr[p] = bs_base + row * (LDA * 2) + koff;
    }

    float acc[2][8][4];
#pragma unroll
    for (int f = 0; f < 2; f++)
#pragma unroll
        for (int nf = 0; nf < 8; nf++)
#pragma unroll
            for (int c = 0; c < 4; c++) acc[f][nf][c] = 0.0f;

    uint32_t* As32 = (uint32_t*)As;
    uint32_t* Bs32 = (uint32_t*)Bs;

    const int steps = Kd / BK;
    for (int s = 0; s < steps; s++) {
        int k0 = s * BK;
#pragma unroll
        for (int v = 0; v < 2; v++) {
            int vec = t + v * 256;
            int row = vec >> 2, q = vec & 3;
            int gm = m0 + row;
            uint4 d = make_uint4(0u, 0u, 0u, 0u);
            if (gm < M)
                d = *(const uint4*)(A2 + (size_t)gm * Kd + k0 + q * 4);
            uint32_t h0 = d.x & 0xffffu, l0 = d.x >> 16;
            uint32_t h1 = d.y & 0xffffu, l1 = d.y >> 16;
            uint32_t h2 = d.z & 0xffffu, l2 = d.z >> 16;
            uint32_t h3 = d.w & 0xffffu, l3 = d.w >> 16;
            uint32_t hp0 = h0 | (h1 << 16), hp1 = h2 | (h3 << 16);
            uint32_t lp0 = l0 | (l1 << 16), lp1 = l2 | (l3 << 16);
            int b32 = row * (LDA / 2) + 2 * q;
            As32[b32 + 0] = hp0;  As32[b32 + 1] = hp1;
            As32[b32 + 8] = lp0;  As32[b32 + 9] = lp1;
            As32[b32 + 16] = hp0; As32[b32 + 17] = hp1;
        }
#pragma unroll
        for (int v = 0; v < 2; v++) {
            int vec = t + v * 256;
            int row = vec >> 2, q = vec & 3;
            uint4 d = *(const uint4*)(B2 + (size_t)(n0 + row) * Kd + k0 + q * 4);
            uint32_t h0 = d.x & 0xffffu, l0 = d.x >> 16;
            uint32_t h1 = d.y & 0xffffu, l1 = d.y >> 16;
            uint32_t h2 = d.z & 0xffffu, l2 = d.z >> 16;
            uint32_t h3 = d.w & 0xffffu, l3 = d.w >> 16;
            uint32_t hp0 = h0 | (h1 << 16), hp1 = h2 | (h3 << 16);
            uint32_t lp0 = l0 | (l1 << 16), lp1 = l2 | (l3 << 16);
            int b32 = row * (LDA / 2) + 2 * q;
            Bs32[b32 + 0] = hp0;  Bs32[b32 + 1] = hp1;
            Bs32[b32 + 8] = hp0;  Bs32[b32 + 9] = hp1;
            Bs32[b32 + 16] = lp0; Bs32[b32 + 17] = lp1;
        }
        __syncthreads();

#pragma unroll
        for (int kb = 0; kb < 3; kb++) {
            uint32_t a[2][4], b[4][4];
#pragma unroll
            for (int f = 0; f < 2; f++) ldsm4(a[f], aaddr[f] + kb * 32);
#pragma unroll
            for (int p = 0; p < 4; p++) ldsm4(b[p], baddr[p] + kb * 32);
#pragma unroll
            for (int f = 0; f < 2; f++)
#pragma unroll
                for (int p = 0; p < 4; p++) {
                    mma16816(acc[f][2 * p],     a[f], b[p][0], b[p][1]);
                    mma16816(acc[f][2 * p + 1], a[f], b[p][2], b[p][3]);
                }
        }
        __syncthreads();
    }

#pragma unroll
    for (int f = 0; f < 2; f++) {
#pragma unroll
        for (int nf = 0; nf < 8; nf++) {
            int col = n0 + n_base + nf * 8 + 2 * (lane & 3);
            float2 bv = *(const float2*)&bias[col];
            int row = m0 + m_base + f * 16 + (lane >> 2);
            if (row < M) {
                float2 o;
                o.x = fmaxf(acc[f][nf][0] + bv.x, 0.0f);
                o.y = fmaxf(acc[f][nf][1] + bv.y, 0.0f);
                *(float2*)(C + (size_t)row * Nc + col) = o;
            }
            int row2 = row + 8;
            if (row2 < M) {
                float2 o;
                o.x = fmaxf(acc[f][nf][2] + bv.x, 0.0f);
                o.y = fmaxf(acc[f][nf][3] + bv.y, 0.0f);
                *(float2*)(C + (size_t)row2 * Nc + col) = o;
            }
        }
    }
}

// out[i] = sigmoid(dot(h[i,:256], Wf) + bf) ; one warp per node
__global__ void final_kernel(const float* __restrict__ Hin,
                             const float* __restrict__ Wf,
                             const float* __restrict__ bf,
                             float* __restrict__ out) {
    int gwarp = (blockIdx.x * blockDim.x + threadIdx.x) >> 5;
    int lane = threadIdx.x & 31;
    if (gwarp >= Nn) return;
    float v = 0.0f;
#pragma unroll
    for (int tc = 0; tc < 8; tc++)
        v = fmaf(Hin[(size_t)gwarp * Hh + lane + tc * 32], Wf[lane + tc * 32], v);
#pragma unroll
    for (int off = 16; off > 0; off >>= 1)
        v += __shfl_xor_sync(FULLM, v, off);
    if (lane == 0) {
        float z = v + bf[0];
        out[gwarp] = 1.0f / (1.0f + expf(-z));
    }
}

// ---------------- host launcher --------------------
extern "C" void kernel_launch(void* const* d_in, const int* in_sizes, int n_in,
                              void* d_out, int out_size) {
    const float* x       = (const float*)d_in[0];
    const float* centers = (const float*)d_in[1];
    const float* W0      = (const float*)d_in[2];
    const float* b0      = (const float*)d_in[3];
    const float* W1      = (const float*)d_in[4];
    const float* b1      = (const float*)d_in[5];
    const float* W2      = (const float*)d_in[6];
    const float* b2      = (const float*)d_in[7];
    const float* Wf      = (const float*)d_in[8];
    const float* bf      = (const float*)d_in[9];
    float* out = (float*)d_out;
    (void)in_sizes; (void)n_in; (void)out_size;

    void *pH, *pS, *pW, *pCnt, *pDeg;
    cudaGetSymbolAddress(&pH, g_bufH);
    cudaGetSymbolAddress(&pS, g_bufS);
    cudaGetSymbolAddress(&pW, g_wt2);
    cudaGetSymbolAddress(&pCnt, g_cellCnt);
    cudaGetSymbolAddress(&pDeg, g_deg);
    float*    Hbuf = (float*)pH;
    uint32_t* Sbuf = (uint32_t*)pS;
    uint32_t* Wbuf = (uint32_t*)pW;

    cudaMemsetAsync(pCnt, 0, NC * sizeof(int));
    cudaMemsetAsync(pDeg, 0, Nn * sizeof(int));
    assign_kernel<<<(Nn + 255) / 256, 256>>>(centers);
    scan_kernel<<<1, 1024>>>();
    scatter_kernel<<<(Nn + 255) / 256, 256>>>(centers);
    knn_kernel<<<(Nn * 32 + 255) / 256, 256>>>();
    deg_kernel<<<(Nn * Kk + 255) / 256, 256>>>();
    srcn_kernel<<<(Nn + 255) / 256, 256>>>();

    dim3 ggrid(Hh / BN, (Nn + BM - 1) / BM);

    // layer 0
    aggregate_kernel<<<Nn, Dd>>>(x, Sbuf, Dd);
    convw_kernel<<<(Dd * Hh + 255) / 256, 256>>>(W0, Dd);
    mma_gemm_kernel<<<ggrid, 256>>>(Sbuf, Wbuf, b0, Hbuf, Nn, Dd, Hh);

    // layer 1
    aggregate_kernel<<<Nn, Hh>>>(Hbuf, Sbuf, Hh);
    convw_kernel<<<(Hh * Hh + 255) / 256, 256>>>(W1, Hh);
    mma_gemm_kernel<<<ggrid, 256>>>(Sbuf, Wbuf, b1, Hbuf, Nn, Hh, Hh);

    // layer 2
    aggregate_kernel<<<Nn, Hh>>>(Hbuf, Sbuf, Hh);
    convw_kernel<<<(Hh * Hh + 255) / 256, 256>>>(W2, Hh);
    mma_gemm_kernel<<<ggrid, 256>>>(Sbuf, Wbuf, b2, Hbuf, Nn, Hh, Hh);

    // final
    final_kernel<<<(Nn * 32 + 255) / 256, 256>>>(Hbuf, Wf, bf, out);
}